// round 8
// baseline (speedup 1.0000x reference)
#include <cuda_runtime.h>
#include <cuda_bf16.h>

// Problem constants
#define BATCH   8
#define IN_P    16
#define REP_C   16
#define OUT_P   32
#define PV      256        // 1024 pixels / 4 (float4 vecs)
#define C_X     256
#define C_OUT1  8192
#define O_PER_C 8

#define OUT1_FLOATS ((size_t)BATCH * C_OUT1 * 1024)   // 67108864 floats

// 256-bit streaming store (Blackwell STG.256)
__device__ __forceinline__ void stg256_cs(float* p,
    float v0, float v1, float v2, float v3,
    float v4, float v5, float v6, float v7)
{
    asm volatile("st.global.cs.v8.f32 [%0], {%1,%2,%3,%4,%5,%6,%7,%8};"
                 :: "l"(p), "f"(v0), "f"(v1), "f"(v2), "f"(v3),
                    "f"(v4), "f"(v5), "f"(v6), "f"(v7) : "memory");
}

// Block = (b, i, o-chunk-of-8). 256 threads: rh = tid>>7 picks the r-half,
// q = tid&127 picks a float8 of pixels. Each thread keeps 8 r-channels x 8
// pixels (64 regs) and issues STG.256 stores — half the store instructions of
// the float4 version. Gate threshold keeps the reference's EXACT sequential
// r=0..15 sum-of-products order via a smem partial-sum handoff between halves.
__global__ __launch_bounds__(256) void qconv_pw_kernel(
    const float4* __restrict__ x,      // (B,256,256) float4
    const float4* __restrict__ x2,     // (B,16,256)  float4
    const float*  __restrict__ w,      // (32,16)
    float* __restrict__ out)           // out1 floats then out2 floats
{
    const int tid = threadIdx.x;
    const int rh  = tid >> 7;          // r-half: 0 -> r 0..7, 1 -> r 8..15
    const int q   = tid & 127;         // float8 pixel index (floats 8q..8q+7)

    const int blk = blockIdx.x;        // 0..511
    const int oc  = blk & 3;           // o-chunk (8 o)
    const int i   = (blk >> 2) & 15;
    const int b   = blk >> 6;

    __shared__ float ws[OUT_P * IN_P];
    __shared__ float sA[O_PER_C * 8 * 128];   // [oo][comp][q] partial sums, 32KB
    __shared__ uint2 mk[128];                 // gate bitmasks per float8

    ws[tid] = w[tid];
    ws[tid + 256] = w[tid + 256];
    __syncthreads();

    // Load this thread's 8 r-channels x 8 pixels (two float4 per r).
    const float4* xc = x + ((size_t)b * C_X + (size_t)(i * REP_C + rh * 8)) * PV + 2 * q;
    float4 xa[8], xb[8];
    #pragma unroll
    for (int rr = 0; rr < 8; rr++) {
        xa[rr] = __ldg(&xc[(size_t)rr * PV]);
        xb[rr] = __ldg(&xc[(size_t)rr * PV + 1]);
    }

    // Phase 1a: rh==0 computes the sequential partial sum over r=0..7.
    if (rh == 0) {
        #pragma unroll
        for (int oo = 0; oo < O_PER_C; oo++) {
            const float wv = ws[(oc * O_PER_C + oo) * IN_P + i];
            float t0=0.f,t1=0.f,t2=0.f,t3=0.f,t4=0.f,t5=0.f,t6=0.f,t7=0.f;
            #pragma unroll
            for (int rr = 0; rr < 8; rr++) {
                t0 += wv * xa[rr].x;  t1 += wv * xa[rr].y;
                t2 += wv * xa[rr].z;  t3 += wv * xa[rr].w;
                t4 += wv * xb[rr].x;  t5 += wv * xb[rr].y;
                t6 += wv * xb[rr].z;  t7 += wv * xb[rr].w;
            }
            float* s = &sA[oo * 8 * 128 + q];
            s[0*128]=t0; s[1*128]=t1; s[2*128]=t2; s[3*128]=t3;
            s[4*128]=t4; s[5*128]=t5; s[6*128]=t6; s[7*128]=t7;
        }
    }
    __syncthreads();

    // Phase 1b: rh==1 continues the SAME sequential chain over r=8..15,
    // producing the gate bits. Bit layout: byte c of the 64-bit mask = pixel
    // component c, bit oo within the byte.
    if (rh == 1) {
        uint2 m = make_uint2(0u, 0u);
        #pragma unroll
        for (int oo = 0; oo < O_PER_C; oo++) {
            const float wv = ws[(oc * O_PER_C + oo) * IN_P + i];
            const float* s = &sA[oo * 8 * 128 + q];
            float t0=s[0*128],t1=s[1*128],t2=s[2*128],t3=s[3*128];
            float t4=s[4*128],t5=s[5*128],t6=s[6*128],t7=s[7*128];
            #pragma unroll
            for (int rr = 0; rr < 8; rr++) {
                t0 += wv * xa[rr].x;  t1 += wv * xa[rr].y;
                t2 += wv * xa[rr].z;  t3 += wv * xa[rr].w;
                t4 += wv * xb[rr].x;  t5 += wv * xb[rr].y;
                t6 += wv * xb[rr].z;  t7 += wv * xb[rr].w;
            }
            m.x |= (t0 > 0.f ? 1u : 0u) << (0*8 + oo);
            m.x |= (t1 > 0.f ? 1u : 0u) << (1*8 + oo);
            m.x |= (t2 > 0.f ? 1u : 0u) << (2*8 + oo);
            m.x |= (t3 > 0.f ? 1u : 0u) << (3*8 + oo);
            m.y |= (t4 > 0.f ? 1u : 0u) << (0*8 + oo);
            m.y |= (t5 > 0.f ? 1u : 0u) << (1*8 + oo);
            m.y |= (t6 > 0.f ? 1u : 0u) << (2*8 + oo);
            m.y |= (t7 > 0.f ? 1u : 0u) << (3*8 + oo);
        }
        mk[q] = m;
    }
    __syncthreads();
    const uint2 m = mk[q];

    // Phase 2: 8 o x 8 r STG.256 streaming-store sweep.
    float* ob = out + ((size_t)b * C_OUT1 + (size_t)(i * REP_C + rh * 8)) * 1024 + 8 * q;
    #pragma unroll
    for (int oo = 0; oo < O_PER_C; oo++) {
        const int o = oc * O_PER_C + oo;
        const float wv = ws[o * IN_P + i];
        const float g0 = ((m.x >> (0*8 + oo)) & 1u) ? wv : 0.f;
        const float g1 = ((m.x >> (1*8 + oo)) & 1u) ? wv : 0.f;
        const float g2 = ((m.x >> (2*8 + oo)) & 1u) ? wv : 0.f;
        const float g3 = ((m.x >> (3*8 + oo)) & 1u) ? wv : 0.f;
        const float g4 = ((m.y >> (0*8 + oo)) & 1u) ? wv : 0.f;
        const float g5 = ((m.y >> (1*8 + oo)) & 1u) ? wv : 0.f;
        const float g6 = ((m.y >> (2*8 + oo)) & 1u) ? wv : 0.f;
        const float g7 = ((m.y >> (3*8 + oo)) & 1u) ? wv : 0.f;

        float* dst = ob + (size_t)o * (C_X * 1024);
        #pragma unroll
        for (int rr = 0; rr < 8; rr++) {
            stg256_cs(dst + (size_t)rr * 1024,
                      g0 * xa[rr].x, g1 * xa[rr].y, g2 * xa[rr].z, g3 * xa[rr].w,
                      g4 * xb[rr].x, g5 * xb[rr].y, g6 * xb[rr].z, g7 * xb[rr].w);
        }
    }

    // Dense 1x1 conv + ReLU path (tiny): i==0 blocks, all 256 threads, one
    // float4 pixel-vec each, sequential ii to match the einsum rounding.
    if (i == 0) {
        const int p = tid;
        const float4* x2b = x2 + (size_t)b * IN_P * PV + p;
        float ax[O_PER_C], ay[O_PER_C], az[O_PER_C], aw[O_PER_C];
        #pragma unroll
        for (int oo = 0; oo < O_PER_C; oo++)
            ax[oo] = ay[oo] = az[oo] = aw[oo] = 0.f;

        #pragma unroll
        for (int ii = 0; ii < IN_P; ii++) {
            const float4 v = __ldg(&x2b[(size_t)ii * PV]);
            #pragma unroll
            for (int oo = 0; oo < O_PER_C; oo++) {
                const float wv = ws[(oc * O_PER_C + oo) * IN_P + ii];
                ax[oo] = fmaf(wv, v.x, ax[oo]);
                ay[oo] = fmaf(wv, v.y, ay[oo]);
                az[oo] = fmaf(wv, v.z, az[oo]);
                aw[oo] = fmaf(wv, v.w, aw[oo]);
            }
        }
        float4* o4 = (float4*)(out + OUT1_FLOATS);
        #pragma unroll
        for (int oo = 0; oo < O_PER_C; oo++) {
            float4 r;
            r.x = fmaxf(ax[oo], 0.f);
            r.y = fmaxf(ay[oo], 0.f);
            r.z = fmaxf(az[oo], 0.f);
            r.w = fmaxf(aw[oo], 0.f);
            o4[((size_t)b * OUT_P + oc * O_PER_C + oo) * PV + p] = r;
        }
    }
}

extern "C" void kernel_launch(void* const* d_in, const int* in_sizes, int n_in,
                              void* d_out, int out_size)
{
    const float4* x  = (const float4*)d_in[0];
    const float4* x2 = (const float4*)d_in[1];
    const float*  w  = (const float*) d_in[2];
    float* out = (float*)d_out;

    qconv_pw_kernel<<<BATCH * IN_P * 4, 256>>>(x, x2, w, out);
}